// round 2
// baseline (speedup 1.0000x reference)
#include <cuda_runtime.h>
#include <math_constants.h>

#define N_NODES 100000
#define N_EDGES 1600000
#define N_GRAPHS 256
#define HDIM 32
#define UPD 128

// ---------------- scratch (device globals; no allocation) ----------------
__device__ float d_aggs[N_NODES];              // layer1 scalar aggregate
__device__ float d_cnt[N_NODES];               // in-degree (for layer3 mean)
__device__ float d_agg32[N_NODES * HDIM];      // 32-wide aggregate buffer
__device__ float d_h1[N_NODES * HDIM];
__device__ float d_h2[N_NODES * HDIM];
__device__ float d_sum[N_GRAPHS * UPD];        // add pool
__device__ float d_maxp[N_GRAPHS * UPD];       // max pool
__device__ float d_gcnt[N_GRAPHS];             // nodes per graph

__device__ __forceinline__ float lrelu(float v) { return v > 0.f ? v : 0.01f * v; }

__device__ __forceinline__ void atomicMaxF(float* addr, float v) {
    if (v >= 0.f) atomicMax((int*)addr, __float_as_int(v));
    else          atomicMin((unsigned int*)addr, __float_as_uint(v));
}

// ---------------- init ----------------
__global__ void k_init() {
    int i = blockIdx.x * blockDim.x + threadIdx.x;
    if (i < N_NODES * HDIM) d_agg32[i] = 0.f;
    if (i < N_NODES) { d_aggs[i] = 0.f; d_cnt[i] = 0.f; }
    if (i < N_GRAPHS * UPD) { d_sum[i] = 0.f; d_maxp[i] = -CUDART_INF_F; }
    if (i < N_GRAPHS) d_gcnt[i] = 0.f;
}

__global__ void k_zero_agg32() {
    int i = blockIdx.x * blockDim.x + threadIdx.x;
    if (i < N_NODES * HDIM) d_agg32[i] = 0.f;
}

// ---------------- graph node counts (batch sorted, hist per block) -------
__global__ void k_gcnt(const int* __restrict__ batch) {
    __shared__ int hist[N_GRAPHS];
    int t = threadIdx.x;
    for (int i = t; i < N_GRAPHS; i += blockDim.x) hist[i] = 0;
    __syncthreads();
    for (int i = blockIdx.x * blockDim.x + t; i < N_NODES; i += gridDim.x * blockDim.x)
        atomicAdd(&hist[batch[i]], 1);
    __syncthreads();
    for (int i = t; i < N_GRAPHS; i += blockDim.x)
        if (hist[i]) atomicAdd(&d_gcnt[i], (float)hist[i]);
}

// ---------------- layer 1: scalar scatter + degree ----------------
__global__ void k_scatter1(const float* __restrict__ x, const int* __restrict__ ei) {
    int e = blockIdx.x * blockDim.x + threadIdx.x;
    if (e >= N_EDGES) return;
    int s = ei[e];
    int d = ei[N_EDGES + e];
    atomicAdd(&d_aggs[d], x[s]);
    atomicAdd(&d_cnt[d], 1.0f);
}

__global__ void k_node1(const float* __restrict__ x,
                        const float* __restrict__ W1l, const float* __restrict__ b1,
                        const float* __restrict__ W1r) {
    int t = blockIdx.x * blockDim.x + threadIdx.x;
    if (t >= N_NODES * HDIM) return;
    int i = t >> 5, j = t & 31;
    d_h1[t] = lrelu(d_aggs[i] * __ldg(&W1l[j]) + __ldg(&b1[j]) + x[i] * __ldg(&W1r[j]));
}

// ---------------- 32-wide edge scatter: warp per edge ----------------
__global__ void k_scatter32(const int* __restrict__ ei, int use_h2) {
    long long gt = (long long)blockIdx.x * blockDim.x + threadIdx.x;
    int w = (int)(gt >> 5);
    int lane = threadIdx.x & 31;
    if (w >= N_EDGES) return;
    int s = __ldg(&ei[w]);
    int d = __ldg(&ei[N_EDGES + w]);
    const float* src = use_h2 ? d_h2 : d_h1;
    atomicAdd(&d_agg32[d * HDIM + lane], src[s * HDIM + lane]);
}

// ---------------- layer 2 node transform ----------------
__global__ void k_node2(const float* __restrict__ W2l, const float* __restrict__ b2,
                        const float* __restrict__ W2r) {
    __shared__ float sWl[HDIM * HDIM], sWr[HDIM * HDIM];
    __shared__ float sA[8 * HDIM], sH[8 * HDIM];
    int t = threadIdx.x;
    for (int i = t; i < HDIM * HDIM; i += 256) { sWl[i] = W2l[i]; sWr[i] = W2r[i]; }
    int base = blockIdx.x * 8;
    int node = base + (t >> 5);
    int j = t & 31;
    if (node < N_NODES) {
        sA[t] = d_agg32[node * HDIM + j];
        sH[t] = d_h1[node * HDIM + j];
    }
    __syncthreads();
    if (node >= N_NODES) return;
    int ns = t >> 5;
    float acc = __ldg(&b2[j]);
#pragma unroll
    for (int k = 0; k < HDIM; k++)
        acc += sA[ns * HDIM + k] * sWl[k * HDIM + j] + sH[ns * HDIM + k] * sWr[k * HDIM + j];
    d_h2[node * HDIM + j] = lrelu(acc);
}

// ---------------- layer 3 (mean) + upsample + pooling (fused) ----------
__global__ void __launch_bounds__(128) k_node3_up_pool(
    const float* __restrict__ W3l, const float* __restrict__ b3,
    const float* __restrict__ W3r, const float* __restrict__ Wu,
    const float* __restrict__ bu, const int* __restrict__ batch) {
    __shared__ float sWl[HDIM * HDIM], sWr[HDIM * HDIM], sWu[HDIM * UPD];
    __shared__ float sA[32 * HDIM], sB[32 * HDIM], sH3[32 * HDIM];
    __shared__ float sb3[HDIM], sbu[UPD];
    __shared__ int sG[32];
    int t = threadIdx.x;
    for (int i = t; i < HDIM * HDIM; i += 128) { sWl[i] = W3l[i]; sWr[i] = W3r[i]; }
    for (int i = t; i < HDIM * UPD; i += 128) sWu[i] = Wu[i];
    if (t < HDIM) sb3[t] = b3[t];
    sbu[t] = bu[t];

    int base = blockIdx.x * 32;
    for (int i = t; i < 32 * HDIM; i += 128) {
        int node = base + (i >> 5);
        if (node < N_NODES) {
            float c = d_cnt[node];
            sA[i] = d_agg32[node * HDIM + (i & 31)] / fmaxf(c, 1.f);
            sB[i] = d_h2[node * HDIM + (i & 31)];
        } else { sA[i] = 0.f; sB[i] = 0.f; }
    }
    if (t < 32) {
        int node = base + t;
        sG[t] = node < N_NODES ? batch[node] : -1;
    }
    __syncthreads();

    // h3 = lrelu(agg/cnt @ W3l + b3 + h2 @ W3r)
    for (int i = t; i < 32 * HDIM; i += 128) {
        int n = i >> 5, j = i & 31;
        float acc = sb3[j];
#pragma unroll
        for (int k = 0; k < HDIM; k++)
            acc += sA[n * HDIM + k] * sWl[k * HDIM + j] + sB[n * HDIM + k] * sWr[k * HDIM + j];
        sH3[i] = lrelu(acc);
    }
    __syncthreads();

    // h = lrelu(h3 @ Wu + bu); accumulate pools in regs, flush on graph change
    int u = t;
    float regS = 0.f, regM = -CUDART_INF_F;
    int gcur = -1;
    for (int n = 0; n < 32; n++) {
        int g = sG[n];
        if (g < 0) break;
        float acc = sbu[u];
#pragma unroll
        for (int k = 0; k < HDIM; k++)
            acc += sH3[n * HDIM + k] * sWu[k * UPD + u];
        acc = lrelu(acc);
        if (g != gcur) {
            if (gcur >= 0) {
                atomicAdd(&d_sum[gcur * UPD + u], regS);
                atomicMaxF(&d_maxp[gcur * UPD + u], regM);
            }
            gcur = g; regS = 0.f; regM = -CUDART_INF_F;
        }
        regS += acc;
        regM = fmaxf(regM, acc);
    }
    if (gcur >= 0) {
        atomicAdd(&d_sum[gcur * UPD + u], regS);
        atomicMaxF(&d_maxp[gcur * UPD + u], regM);
    }
}

// ---------------- final MLP per graph ----------------
__global__ void k_final(const float* __restrict__ Wf1, const float* __restrict__ bf1,
                        const float* __restrict__ Wf2, const float* __restrict__ bf2,
                        float* __restrict__ out) {
    __shared__ float sZ[3 * UPD], sT[UPD];
    int g = blockIdx.x, t = threadIdx.x;  // 128 threads
    float c = d_gcnt[g];
    float s = d_sum[g * UPD + t];
    sZ[t] = s / fmaxf(c, 1.f);          // mean pool
    sZ[UPD + t] = d_maxp[g * UPD + t];  // max pool
    sZ[2 * UPD + t] = s;                // add pool
    __syncthreads();
    float acc = __ldg(&bf1[t]);
#pragma unroll 8
    for (int k = 0; k < 3 * UPD; k++)
        acc += sZ[k] * __ldg(&Wf1[k * UPD + t]);
    sT[t] = lrelu(acc);
    __syncthreads();
    if (t < 51) {
        float o = __ldg(&bf2[t]);
#pragma unroll 8
        for (int k = 0; k < UPD; k++)
            o += sT[k] * __ldg(&Wf2[k * 51 + t]);
        out[g * 51 + t] = o;
    }
}

// ---------------- launch ----------------
extern "C" void kernel_launch(void* const* d_in, const int* in_sizes, int n_in,
                              void* d_out, int out_size) {
    const float* x     = (const float*)d_in[0];
    const int* ei      = (const int*)d_in[1];    // int32! (JAX x64 disabled)
    const int* batch   = (const int*)d_in[2];    // int32!
    const float* W1l = (const float*)d_in[3];
    const float* b1  = (const float*)d_in[4];
    const float* W1r = (const float*)d_in[5];
    const float* W2l = (const float*)d_in[6];
    const float* b2  = (const float*)d_in[7];
    const float* W2r = (const float*)d_in[8];
    const float* W3l = (const float*)d_in[9];
    const float* b3  = (const float*)d_in[10];
    const float* W3r = (const float*)d_in[11];
    const float* Wu  = (const float*)d_in[12];
    const float* bu  = (const float*)d_in[13];
    const float* Wf1 = (const float*)d_in[14];
    const float* bf1 = (const float*)d_in[15];
    const float* Wf2 = (const float*)d_in[16];
    const float* bf2 = (const float*)d_in[17];
    float* out = (float*)d_out;

    k_init<<<(N_NODES * HDIM + 255) / 256, 256>>>();
    k_gcnt<<<64, 256>>>(batch);
    k_scatter1<<<(N_EDGES + 255) / 256, 256>>>(x, ei);
    k_node1<<<(N_NODES * HDIM + 255) / 256, 256>>>(x, W1l, b1, W1r);
    k_scatter32<<<(int)(((long long)N_EDGES * 32 + 255) / 256), 256>>>(ei, 0);
    k_node2<<<(N_NODES + 7) / 8, 256>>>(W2l, b2, W2r);
    k_zero_agg32<<<(N_NODES * HDIM + 255) / 256, 256>>>();
    k_scatter32<<<(int)(((long long)N_EDGES * 32 + 255) / 256), 256>>>(ei, 1);
    k_node3_up_pool<<<(N_NODES + 31) / 32, 128>>>(W3l, b3, W3r, Wu, bu, batch);
    k_final<<<N_GRAPHS, 128>>>(Wf1, bf1, Wf2, bf2, out);
}

// round 3
// speedup vs baseline: 1.4658x; 1.4658x over previous
#include <cuda_runtime.h>
#include <math_constants.h>

#define N_NODES 100000
#define N_EDGES 1600000
#define N_GRAPHS 256
#define HDIM 32
#define UPD 128

// ---------------- scratch (device globals; no allocation) ----------------
__device__ float d_aggcnt[N_NODES * 2];        // interleaved {agg, cnt} for layer1
__device__ float d_agg32[N_NODES * HDIM];      // layer2 aggregate
__device__ float d_agg32b[N_NODES * HDIM];     // layer3 aggregate (separate: no re-zero)
__device__ float d_h1[N_NODES * HDIM];
__device__ float d_h2[N_NODES * HDIM];
__device__ float d_sum[N_GRAPHS * UPD];        // add pool
__device__ float d_maxp[N_GRAPHS * UPD];       // max pool
__device__ float d_gcnt[N_GRAPHS];             // nodes per graph

__device__ __forceinline__ float lrelu(float v) { return v > 0.f ? v : 0.01f * v; }

__device__ __forceinline__ void atomicMaxF(float* addr, float v) {
    if (v >= 0.f) atomicMax((int*)addr, __float_as_int(v));
    else          atomicMin((unsigned int*)addr, __float_as_uint(v));
}

__device__ __forceinline__ void red_add_v4(float* p, float4 v) {
    asm volatile("red.global.add.v4.f32 [%0], {%1, %2, %3, %4};"
                 :: "l"(p), "f"(v.x), "f"(v.y), "f"(v.z), "f"(v.w) : "memory");
}

__device__ __forceinline__ void red_add_v2(float* p, float a, float b) {
    asm volatile("red.global.add.v2.f32 [%0], {%1, %2};"
                 :: "l"(p), "f"(a), "f"(b) : "memory");
}

// ---------------- init (zero everything once) ----------------
__global__ void k_init() {
    int i = blockIdx.x * blockDim.x + threadIdx.x;
    if (i < N_NODES * HDIM) { d_agg32[i] = 0.f; d_agg32b[i] = 0.f; }
    if (i < N_NODES * 2) d_aggcnt[i] = 0.f;
    if (i < N_GRAPHS * UPD) { d_sum[i] = 0.f; d_maxp[i] = -CUDART_INF_F; }
    if (i < N_GRAPHS) d_gcnt[i] = 0.f;
}

// ---------------- graph node counts (batch sorted, hist per block) -------
__global__ void k_gcnt(const int* __restrict__ batch) {
    __shared__ int hist[N_GRAPHS];
    int t = threadIdx.x;
    for (int i = t; i < N_GRAPHS; i += blockDim.x) hist[i] = 0;
    __syncthreads();
    for (int i = blockIdx.x * blockDim.x + t; i < N_NODES; i += gridDim.x * blockDim.x)
        atomicAdd(&hist[batch[i]], 1);
    __syncthreads();
    for (int i = t; i < N_GRAPHS; i += blockDim.x)
        if (hist[i]) atomicAdd(&d_gcnt[i], (float)hist[i]);
}

// ---------------- layer 1: scalar scatter + degree (one v2 red per edge) --
__global__ void k_scatter1(const float* __restrict__ x, const int* __restrict__ ei) {
    int e = blockIdx.x * blockDim.x + threadIdx.x;
    if (e >= N_EDGES) return;
    int s = __ldg(&ei[e]);
    int d = __ldg(&ei[N_EDGES + e]);
    red_add_v2(&d_aggcnt[2 * d], __ldg(&x[s]), 1.0f);
}

__global__ void k_node1(const float* __restrict__ x,
                        const float* __restrict__ W1l, const float* __restrict__ b1,
                        const float* __restrict__ W1r) {
    int t = blockIdx.x * blockDim.x + threadIdx.x;
    if (t >= N_NODES * HDIM) return;
    int i = t >> 5, j = t & 31;
    d_h1[t] = lrelu(d_aggcnt[2 * i] * __ldg(&W1l[j]) + __ldg(&b1[j]) + x[i] * __ldg(&W1r[j]));
}

// ---------------- 32-wide edge scatter: 8 threads/edge, v4 red ----------
__global__ void k_scatter32_v4(const int* __restrict__ ei, int phase) {
    long long gt = (long long)blockIdx.x * blockDim.x + threadIdx.x;
    int e = (int)(gt >> 3);
    int q = (int)(gt & 7);
    if (e >= N_EDGES) return;
    int s = __ldg(&ei[e]);
    int d = __ldg(&ei[N_EDGES + e]);
    const float* src = phase ? d_h2 : d_h1;
    float* dst = phase ? d_agg32b : d_agg32;
    float4 v = *(const float4*)&src[s * HDIM + q * 4];
    red_add_v4(&dst[d * HDIM + q * 4], v);
}

// ---------------- layer 2 node transform ----------------
__global__ void k_node2(const float* __restrict__ W2l, const float* __restrict__ b2,
                        const float* __restrict__ W2r) {
    __shared__ float sWl[HDIM * HDIM], sWr[HDIM * HDIM];
    __shared__ float sA[8 * HDIM], sH[8 * HDIM];
    int t = threadIdx.x;
    for (int i = t; i < HDIM * HDIM; i += 256) { sWl[i] = W2l[i]; sWr[i] = W2r[i]; }
    int base = blockIdx.x * 8;
    int node = base + (t >> 5);
    int j = t & 31;
    if (node < N_NODES) {
        sA[t] = d_agg32[node * HDIM + j];
        sH[t] = d_h1[node * HDIM + j];
    }
    __syncthreads();
    if (node >= N_NODES) return;
    int ns = t >> 5;
    float acc = __ldg(&b2[j]);
#pragma unroll
    for (int k = 0; k < HDIM; k++)
        acc += sA[ns * HDIM + k] * sWl[k * HDIM + j] + sH[ns * HDIM + k] * sWr[k * HDIM + j];
    d_h2[node * HDIM + j] = lrelu(acc);
}

// ---------------- layer 3 (mean) + upsample + pooling (fused) ----------
__global__ void __launch_bounds__(128) k_node3_up_pool(
    const float* __restrict__ W3l, const float* __restrict__ b3,
    const float* __restrict__ W3r, const float* __restrict__ Wu,
    const float* __restrict__ bu, const int* __restrict__ batch) {
    __shared__ float sWl[HDIM * HDIM], sWr[HDIM * HDIM], sWu[HDIM * UPD];
    __shared__ float sA[32 * HDIM], sB[32 * HDIM], sH3[32 * HDIM];
    __shared__ float sb3[HDIM], sbu[UPD];
    __shared__ int sG[32];
    int t = threadIdx.x;
    for (int i = t; i < HDIM * HDIM; i += 128) { sWl[i] = W3l[i]; sWr[i] = W3r[i]; }
    for (int i = t; i < HDIM * UPD; i += 128) sWu[i] = Wu[i];
    if (t < HDIM) sb3[t] = b3[t];
    sbu[t] = bu[t];

    int base = blockIdx.x * 32;
    for (int i = t; i < 32 * HDIM; i += 128) {
        int node = base + (i >> 5);
        if (node < N_NODES) {
            float c = d_aggcnt[2 * node + 1];
            sA[i] = d_agg32b[node * HDIM + (i & 31)] / fmaxf(c, 1.f);
            sB[i] = d_h2[node * HDIM + (i & 31)];
        } else { sA[i] = 0.f; sB[i] = 0.f; }
    }
    if (t < 32) {
        int node = base + t;
        sG[t] = node < N_NODES ? batch[node] : -1;
    }
    __syncthreads();

    // h3 = lrelu(agg/cnt @ W3l + b3 + h2 @ W3r)
    for (int i = t; i < 32 * HDIM; i += 128) {
        int n = i >> 5, j = i & 31;
        float acc = sb3[j];
#pragma unroll
        for (int k = 0; k < HDIM; k++)
            acc += sA[n * HDIM + k] * sWl[k * HDIM + j] + sB[n * HDIM + k] * sWr[k * HDIM + j];
        sH3[i] = lrelu(acc);
    }
    __syncthreads();

    // h = lrelu(h3 @ Wu + bu); accumulate pools in regs, flush on graph change
    int u = t;
    float regS = 0.f, regM = -CUDART_INF_F;
    int gcur = -1;
    for (int n = 0; n < 32; n++) {
        int g = sG[n];
        if (g < 0) break;
        float acc = sbu[u];
#pragma unroll
        for (int k = 0; k < HDIM; k++)
            acc += sH3[n * HDIM + k] * sWu[k * UPD + u];
        acc = lrelu(acc);
        if (g != gcur) {
            if (gcur >= 0) {
                atomicAdd(&d_sum[gcur * UPD + u], regS);
                atomicMaxF(&d_maxp[gcur * UPD + u], regM);
            }
            gcur = g; regS = 0.f; regM = -CUDART_INF_F;
        }
        regS += acc;
        regM = fmaxf(regM, acc);
    }
    if (gcur >= 0) {
        atomicAdd(&d_sum[gcur * UPD + u], regS);
        atomicMaxF(&d_maxp[gcur * UPD + u], regM);
    }
}

// ---------------- final MLP per graph ----------------
__global__ void k_final(const float* __restrict__ Wf1, const float* __restrict__ bf1,
                        const float* __restrict__ Wf2, const float* __restrict__ bf2,
                        float* __restrict__ out) {
    __shared__ float sZ[3 * UPD], sT[UPD];
    int g = blockIdx.x, t = threadIdx.x;  // 128 threads
    float c = d_gcnt[g];
    float s = d_sum[g * UPD + t];
    sZ[t] = s / fmaxf(c, 1.f);          // mean pool
    sZ[UPD + t] = d_maxp[g * UPD + t];  // max pool
    sZ[2 * UPD + t] = s;                // add pool
    __syncthreads();
    float acc = __ldg(&bf1[t]);
#pragma unroll 8
    for (int k = 0; k < 3 * UPD; k++)
        acc += sZ[k] * __ldg(&Wf1[k * UPD + t]);
    sT[t] = lrelu(acc);
    __syncthreads();
    if (t < 51) {
        float o = __ldg(&bf2[t]);
#pragma unroll 8
        for (int k = 0; k < UPD; k++)
            o += sT[k] * __ldg(&Wf2[k * 51 + t]);
        out[g * 51 + t] = o;
    }
}

// ---------------- launch ----------------
extern "C" void kernel_launch(void* const* d_in, const int* in_sizes, int n_in,
                              void* d_out, int out_size) {
    const float* x     = (const float*)d_in[0];
    const int* ei      = (const int*)d_in[1];    // int32 (JAX x64 disabled)
    const int* batch   = (const int*)d_in[2];    // int32
    const float* W1l = (const float*)d_in[3];
    const float* b1  = (const float*)d_in[4];
    const float* W1r = (const float*)d_in[5];
    const float* W2l = (const float*)d_in[6];
    const float* b2  = (const float*)d_in[7];
    const float* W2r = (const float*)d_in[8];
    const float* W3l = (const float*)d_in[9];
    const float* b3  = (const float*)d_in[10];
    const float* W3r = (const float*)d_in[11];
    const float* Wu  = (const float*)d_in[12];
    const float* bu  = (const float*)d_in[13];
    const float* Wf1 = (const float*)d_in[14];
    const float* bf1 = (const float*)d_in[15];
    const float* Wf2 = (const float*)d_in[16];
    const float* bf2 = (const float*)d_in[17];
    float* out = (float*)d_out;

    k_init<<<(N_NODES * HDIM + 255) / 256, 256>>>();
    k_gcnt<<<64, 256>>>(batch);
    k_scatter1<<<(N_EDGES + 255) / 256, 256>>>(x, ei);
    k_node1<<<(N_NODES * HDIM + 255) / 256, 256>>>(x, W1l, b1, W1r);
    int sblocks = (int)(((long long)N_EDGES * 8 + 255) / 256);
    k_scatter32_v4<<<sblocks, 256>>>(ei, 0);
    k_node2<<<(N_NODES + 7) / 8, 256>>>(W2l, b2, W2r);
    k_scatter32_v4<<<sblocks, 256>>>(ei, 1);
    k_node3_up_pool<<<(N_NODES + 31) / 32, 128>>>(W3l, b3, W3r, Wu, bu, batch);
    k_final<<<N_GRAPHS, 128>>>(Wf1, bf1, Wf2, bf2, out);
}